// round 16
// baseline (speedup 1.0000x reference)
#include <cuda_runtime.h>

#define TPB       512
#define NRT       128                  // row-tiles of 128 rows
#define ROWS_TILE 128
#define NJP       16                   // j-pieces of 256
#define JP_LEN    256
#define CHUNKS    4                    // intra-unit j split: 4 x 64 j
#define JSUB      64
#define NUNITS    (NRT * NJP)          // 2048
#define NPIECE    (NJP * CHUNKS)       // 64 partials per row
#define MAX_BATCH 16384

// Partial sums: piece p = jp*4+chunk covers j in [p*64, p*64+64).
__device__ float g_partial[NPIECE][MAX_BATCH * 3];   // 12.6 MB, L2-resident

__global__ void __launch_bounds__(TPB, 1)
tps_main(const float* __restrict__ u,
         const float* __restrict__ cp,
         const float* __restrict__ w,
         int batch, int n) {
    __shared__ float4 s_c[JP_LEN];     // {-2cx,-2cy,-2cz,|c|^2}
    __shared__ float4 s_w[JP_LEN];     // {w0,w1,w2,0}

    const int tid = threadIdx.x;
    const int bid = blockIdx.x;
    const int G   = gridDim.x;

    // Contiguous unit range, jp-major: unit = jp*NRT + rt.
    // Range length <= 14 < NRT, so at most one jp boundary per CTA.
    const int u0 = (int)(((long long)bid       * NUNITS) / G);
    const int u1 = (int)(((long long)(bid + 1) * NUNITS) / G);

    const int row_local = tid & (ROWS_TILE - 1);   // 0..127
    const int chunk     = tid >> 7;                // 0..3
    const int jb        = chunk * JSUB;

    int cur_jp = -1;

    for (int unit = u0; unit < u1; ++unit) {
        const int jp = unit >> 7;              // unit / NRT
        const int rt = unit & (NRT - 1);       // unit % NRT

        if (jp != cur_jp) {
            __syncthreads();                   // drain readers of old slice
            if (tid < JP_LEN) {
                int j = jp * JP_LEN + tid;
                float cx = cp[3 * j + 0];
                float cy = cp[3 * j + 1];
                float cz = cp[3 * j + 2];
                float c2 = fmaf(cx, cx, fmaf(cy, cy, cz * cz));
                s_c[tid] = make_float4(-2.0f * cx, -2.0f * cy, -2.0f * cz, c2);
                s_w[tid] = make_float4(w[3 * j + 0], w[3 * j + 1], w[3 * j + 2], 0.0f);
            }
            cur_jp = jp;
            __syncthreads();
        }

        const int row = rt * ROWS_TILE + row_local;
        float ux = u[3 * row + 0];
        float uy = u[3 * row + 1];
        float uz = u[3 * row + 2];
        float u2 = fmaf(ux, ux, fmaf(uy, uy, uz * uz));

        float a0 = 0.0f, a1 = 0.0f, a2 = 0.0f;

        #pragma unroll 8
        for (int jj = jb; jj < jb + JSUB; ++jj) {
            float4 c  = s_c[jj];
            float4 wj = s_w[jj];
            // sq = |u|^2 + |c|^2 - 2 u.c  (expanded form, matches reference cdist)
            float sq = fmaf(c.x, ux, fmaf(c.y, uy, fmaf(c.z, uz, u2 + c.w)));
            sq = fmaxf(sq, 1e-20f);       // absorbs r<EPS -> 0 branch (k ~ -6.6e-9)
            float r, lg;
            asm("sqrt.approx.f32 %0, %1;" : "=f"(r)  : "f"(sq));
            asm("lg2.approx.f32 %0, %1;"  : "=f"(lg) : "f"(sq));
            float k = r * lg;             // true k = 0.5*ln2 * sqrt(sq)*lg2(sq)
            a0 = fmaf(k, wj.x, a0);
            a1 = fmaf(k, wj.y, a1);
            a2 = fmaf(k, wj.z, a2);
        }

        // Independent partial: no reduction, no sync, no atomics.
        float* gp = &g_partial[jp * CHUNKS + chunk][3 * row];
        gp[0] = a0; gp[1] = a1; gp[2] = a2;
    }
}

__global__ void __launch_bounds__(256, 4)
tps_fixup(const float* __restrict__ u,
          const float* __restrict__ poly,
          float* __restrict__ out,
          int batch) {
    int idx = blockIdx.x * 256 + threadIdx.x;     // output element
    bool ok = idx < batch * 3;
    int row  = ok ? idx / 3 : 0;
    int comp = idx - 3 * row;

    // ---- pre-dependency work: runs while tps_main is still executing ----
    float vx = u[3 * row + 0];
    float vy = u[3 * row + 1];
    float vz = u[3 * row + 2];
    float pp = poly[comp]
             + fmaf(vx, poly[3 + comp],
               fmaf(vy, poly[6 + comp], vz * poly[9 + comp]));

    // ---- wait for tps_main's partials to be visible ----
    cudaGridDependencySynchronize();

    float sum = 0.0f;
    #pragma unroll
    for (int p = 0; p < NPIECE; ++p)              // fixed order: deterministic
        sum += g_partial[p][idx];

    const float C = 0.34657359027997264f;         // 0.5 * ln(2)
    if (ok)
        out[idx] = fmaf(C, sum, pp);
}

extern "C" void kernel_launch(void* const* d_in, const int* in_sizes, int n_in,
                              void* d_out, int out_size) {
    const float* u    = (const float*)d_in[0];
    const float* cp   = (const float*)d_in[1];
    const float* w    = (const float*)d_in[2];
    const float* poly = (const float*)d_in[3];
    float* out = (float*)d_out;

    int batch = in_sizes[0] / 3;
    int n     = in_sizes[1] / 3;

    int sms = 148;
    cudaDeviceGetAttribute(&sms, cudaDevAttrMultiProcessorCount, 0);
    if (sms < 1) sms = 148;

    tps_main<<<sms, TPB>>>(u, cp, w, batch, n);

    // Fixup as a programmatic dependent launch: its grid launches + runs the
    // pre-sync section (u/poly loads) overlapped with tps_main's tail; the
    // partial reads happen only after cudaGridDependencySynchronize().
    cudaLaunchConfig_t cfg = {};
    cfg.gridDim  = dim3((batch * 3 + 255) / 256, 1, 1);
    cfg.blockDim = dim3(256, 1, 1);
    cudaLaunchAttribute attrs[1];
    attrs[0].id = cudaLaunchAttributeProgrammaticStreamSerialization;
    attrs[0].val.programmaticStreamSerializationAllowed = 1;
    cfg.attrs    = attrs;
    cfg.numAttrs = 1;
    cudaLaunchKernelEx(&cfg, tps_fixup, u, poly, out, batch);
}